// round 6
// baseline (speedup 1.0000x reference)
#include <cuda_runtime.h>

// ---------------------------------------------------------------------------
// KNNGaussianBlur: out = GaussianBlur_sigma4_radius12(img[0]) with replicate
// padding. (/max ... *max cancels -> no reduction.)
//
// R6: fused V->smem->H with
//  * packed fma.rn.f32x2 (2 FMA/instr, weights broadcast (w,w): 13 u64 consts)
//  * smem holds V output as y-PAIR float2 planes -> H's packed operands come
//    straight out of LDS.128, zero packing instructions
//  * 16B-slot XOR swizzle (u ^ ((u>>3)&7)) -> conflict-free LDS/STS
//  * V: 64 cols x 2 ygroups of 8 rows (32-row stream) -> LDG wf halved vs R5
//  * H: thread owns 8 px x 2 rows; 16 LDS.128 -> 16 px (4 LDS per f4-out vs 7)
// ---------------------------------------------------------------------------

#define H_IMG 4096
#define W_IMG 4096
#define C_IMG 3
#define RADIUS 12

__device__ constexpr float KW[13] = {
    0.09990835f, 0.09683452f, 0.08816879f, 0.07541476f, 0.06059747f,
    0.04574137f, 0.03243549f, 0.02160670f, 0.01352113f, 0.00794866f,
    0.00438966f, 0.00227733f, 0.00110988f
};

__device__ __forceinline__ unsigned long long pack2(float lo, float hi) {
    unsigned long long r;
    asm("mov.b64 %0, {%1, %2};" : "=l"(r) : "f"(lo), "f"(hi));
    return r;
}
__device__ __forceinline__ void unpack2(unsigned long long v, float& lo, float& hi) {
    asm("mov.b64 {%0, %1}, %2;" : "=f"(lo), "=f"(hi) : "l"(v));
}
__device__ __forceinline__ void fma2(unsigned long long& acc,
                                     unsigned long long a, unsigned long long w) {
    asm("fma.rn.f32x2 %0, %1, %2, %0;" : "+l"(acc) : "l"(a), "l"(w));
}

constexpr int OW4     = 58;                 // output f4 per tile (232 px)
constexpr int OW      = OW4 * 4;            // 232
constexpr int VW4     = 64;                 // V-tile width in f4 (232 + 24 halo)
constexpr int OH      = 16;                 // output rows per tile (8 row-pairs)
constexpr int TILES_X = (W_IMG + OW - 1) / OW;   // 18  (232*17+232=4176; last tile 152px)

__global__ __launch_bounds__(256)
void fused_blur_kernel(const float* __restrict__ in, float* __restrict__ out) {
    // 8 row-pair planes x 256 x-positions stored as float2 (row even, row odd),
    // 16B slots swizzled. Plane stride 512 floats = 2KB. Total 16KB.
    __shared__ float vt[8 * 512];

    const int bx  = blockIdx.x;
    const int y0  = blockIdx.y * OH;
    const int cch = blockIdx.z;
    const int t   = threadIdx.x;

    // broadcast weight pairs (w,w) -- 13 u64 registers, live across both phases
    unsigned long long w2[13];
#pragma unroll
    for (int k = 0; k < 13; ++k) w2[k] = pack2(KW[k], KW[k]);

    const float* inc = in + (size_t)cch * ((size_t)H_IMG * W_IMG);

    // ------------------------- Vertical phase --------------------------
    // 128 threads: 64 f4-cols x 2 ygroups (8 rows each). Stream 32 input
    // rows with row clamp (= replicate pad). Accumulate in x-pairs (free:
    // LDG.128 viewed as ulonglong2). 400 FFMA2 / thread.
    if (t < 128) {
        int c   = t & 63;
        int yg  = t >> 6;                    // 0..1
        int yb  = y0 + 8 * yg;
        int gfc = OW4 * bx - 3 + c;          // global f4 col (may be OOB)
        bool inb = (gfc >= 0) && (gfc < W_IMG / 4);
        int  cadj = gfc < 0 ? 0 : W_IMG - 1; // edge float col for broadcast

        unsigned long long aLo[8], aHi[8];
#pragma unroll
        for (int i = 0; i < 8; ++i) { aLo[i] = 0ull; aHi[i] = 0ull; }

#pragma unroll
        for (int r = 0; r < 32; ++r) {       // rows yb-12 .. yb+19
            int row = yb - RADIUS + r;
            row = row < 0 ? 0 : (row > H_IMG - 1 ? H_IMG - 1 : row);
            unsigned long long vlo, vhi;
            if (inb) {
                ulonglong2 v = __ldg((const ulonglong2*)inc
                                     + (size_t)row * (W_IMG / 4) + gfc);
                vlo = v.x; vhi = v.y;
            } else {
                float s = __ldg(inc + (size_t)row * W_IMG + cadj);
                vlo = pack2(s, s); vhi = vlo;
            }
#pragma unroll
            for (int i = 0; i < 8; ++i) {
                int d = r - RADIUS - i;      // compile-time per (r,i)
                if (d >= -RADIUS && d <= RADIUS) {
                    unsigned long long w = w2[d < 0 ? -d : d];
                    fma2(aLo[i], vlo, w);
                    fma2(aHi[i], vhi, w);
                }
            }
        }

        // Transpose-store: y-pair interleave, swizzled 16B slots.
        // Slot u holds float2 for x=2u,2u+1: (r_even[x], r_odd[x], r_even[x+1], r_odd[x+1]).
#pragma unroll
        for (int j = 0; j < 4; ++j) {        // row-pair within ygroup
            float a0x, a0y, a0z, a0w, a1x, a1y, a1z, a1w;
            unpack2(aLo[2 * j],     a0x, a0y); unpack2(aHi[2 * j],     a0z, a0w);
            unpack2(aLo[2 * j + 1], a1x, a1y); unpack2(aHi[2 * j + 1], a1z, a1w);
            int plane = 4 * yg + j;
            int u0 = 2 * c, u1 = 2 * c + 1;
            int p0 = u0 ^ ((u0 >> 3) & 7);
            int p1 = u1 ^ ((u1 >> 3) & 7);
            *(float4*)&vt[plane * 512 + p0 * 4] = make_float4(a0x, a1x, a0y, a1y);
            *(float4*)&vt[plane * 512 + p1 * 4] = make_float4(a0z, a1z, a0w, a1w);
        }
    }

    __syncthreads();

    // ------------------------ Horizontal phase -------------------------
    // 232 threads: 8 row-pairs x 29 x-slots (8 px each, 2 rows). Window =
    // smem x in [8s, 8s+31] = 16 swizzled LDS.128; every loaded u64 is a
    // ready y-pair operand. 200 FFMA2 / thread for 16 output px.
    {
        int rp = t >> 5;                     // row-pair 0..7 (one warp each)
        int s  = t & 31;                     // x-slot
        int X0 = OW * bx + 8 * s;            // global float col of px 0
        if (s < 29 && X0 < W_IMG) {          // last tile: exactly s<19 valid
            unsigned long long acc[8];
#pragma unroll
            for (int p = 0; p < 8; ++p) acc[p] = 0ull;

            const float* pl = &vt[rp * 512];
#pragma unroll
            for (int m = 0; m < 16; ++m) {
                int u  = 4 * s + m;
                int ph = u ^ ((u >> 3) & 7);
                ulonglong2 q = *(const ulonglong2*)&pl[ph * 4];
#pragma unroll
                for (int k = 0; k < 2; ++k) {
                    unsigned long long f = k ? q.y : q.x;
                    int xo = 2 * m + k;      // smem x offset - 8s (0..31)
#pragma unroll
                    for (int p = 0; p < 8; ++p) {
                        int d = xo - RADIUS - p;   // compile-time
                        if (d >= -RADIUS && d <= RADIUS)
                            fma2(acc[p], f, w2[d < 0 ? -d : d]);
                    }
                }
            }

            float lo[8], hi[8];
#pragma unroll
            for (int p = 0; p < 8; ++p) unpack2(acc[p], lo[p], hi[p]);
            size_t ob = (size_t)cch * ((size_t)H_IMG * W_IMG)
                      + (size_t)(y0 + 2 * rp) * W_IMG + X0;
            *(float4*)&out[ob]             = make_float4(lo[0], lo[1], lo[2], lo[3]);
            *(float4*)&out[ob + 4]         = make_float4(lo[4], lo[5], lo[6], lo[7]);
            *(float4*)&out[ob + W_IMG]     = make_float4(hi[0], hi[1], hi[2], hi[3]);
            *(float4*)&out[ob + W_IMG + 4] = make_float4(hi[4], hi[5], hi[6], hi[7]);
        }
    }
}

// ------------------------------ entry point --------------------------------
extern "C" void kernel_launch(void* const* d_in, const int* in_sizes, int n_in,
                              void* d_out, int out_size) {
    const float* img = (const float*)d_in[0];    // [1,3,4096,4096] fp32
    float* out = (float*)d_out;                  // [3,4096,4096] fp32

    dim3 grid(TILES_X, H_IMG / OH, C_IMG);       // (18, 256, 3)
    fused_blur_kernel<<<grid, 256>>>(img, out);
}

// round 7
// speedup vs baseline: 1.2225x; 1.2225x over previous
#include <cuda_runtime.h>

// ---------------------------------------------------------------------------
// KNNGaussianBlur: out = GaussianBlur_sigma4_radius12(img[0]) with replicate
// padding. (/max ... *max cancels -> no reduction.)
//
// R7: fused V->smem->H, fixing R6's stall collapse:
//  * V phase uses ALL 256 threads (64 f4-cols x 4 ygroups of 4 rows, 28-row
//    stream) -- R5's proven latency-friendly shape -- but with f32x2 FMAs
//    (200 FMA2/thread, acc = 8 u64 = 16 regs vs R6's 32).
//  * smem: V output stored as y-pair float2, 16B slots XOR-swizzled
//    (u ^ ((u>>3)&7)) -> conflict-free STS/LDS (verified per 8-lane phase).
//  * H (unchanged from R6): thread = 8px x 2 rows, 16 LDS.128 + 200 FMA2;
//    every LDS'd u64 is a ready (row_even, row_odd) operand, same weight.
// ---------------------------------------------------------------------------

#define H_IMG 4096
#define W_IMG 4096
#define C_IMG 3
#define RADIUS 12

__device__ constexpr float KW[13] = {
    0.09990835f, 0.09683452f, 0.08816879f, 0.07541476f, 0.06059747f,
    0.04574137f, 0.03243549f, 0.02160670f, 0.01352113f, 0.00794866f,
    0.00438966f, 0.00227733f, 0.00110988f
};

__device__ __forceinline__ unsigned long long pack2(float lo, float hi) {
    unsigned long long r;
    asm("mov.b64 %0, {%1, %2};" : "=l"(r) : "f"(lo), "f"(hi));
    return r;
}
__device__ __forceinline__ void unpack2(unsigned long long v, float& lo, float& hi) {
    asm("mov.b64 {%0, %1}, %2;" : "=f"(lo), "=f"(hi) : "l"(v));
}
__device__ __forceinline__ void fma2(unsigned long long& acc,
                                     unsigned long long a, unsigned long long w) {
    asm("fma.rn.f32x2 %0, %1, %2, %0;" : "+l"(acc) : "l"(a), "l"(w));
}

constexpr int OW4     = 58;                 // output f4 per tile (232 px)
constexpr int OW      = OW4 * 4;            // 232
constexpr int OH      = 16;                 // output rows per tile (8 row-pairs)
constexpr int TILES_X = (W_IMG + OW - 1) / OW;   // 18

__global__ __launch_bounds__(256)
void fused_blur_kernel(const float* __restrict__ in, float* __restrict__ out) {
    // 8 row-pair planes x 128 swizzled 16B slots (2 x-positions each) = 16KB.
    __shared__ float vt[8 * 512];

    const int bx  = blockIdx.x;
    const int y0  = blockIdx.y * OH;
    const int cch = blockIdx.z;
    const int t   = threadIdx.x;

    // broadcast weight pairs (w,w): 13 u64 regs, live across both phases
    unsigned long long w2[13];
#pragma unroll
    for (int k = 0; k < 13; ++k) w2[k] = pack2(KW[k], KW[k]);

    const float* inc = in + (size_t)cch * ((size_t)H_IMG * W_IMG);

    // ------------------------- Vertical phase --------------------------
    // 256 threads: 64 f4-cols x 4 ygroups of 4 rows. Stream 28 input rows
    // (row clamp = replicate pad). Column clamp: OOB f4 -> broadcast edge px.
    {
        int c   = t & 63;
        int yg  = t >> 6;                    // 0..3
        int yb  = y0 + 4 * yg;
        int gfc = OW4 * bx - 3 + c;          // global f4 col (may be OOB)
        bool inb  = (gfc >= 0) && (gfc < W_IMG / 4);
        int  cadj = gfc < 0 ? 0 : W_IMG - 1; // edge float col for broadcast

        unsigned long long aLo[4], aHi[4];
#pragma unroll
        for (int i = 0; i < 4; ++i) { aLo[i] = 0ull; aHi[i] = 0ull; }

#pragma unroll
        for (int r = 0; r < 28; ++r) {       // rows yb-12 .. yb+15
            int row = yb - RADIUS + r;
            row = row < 0 ? 0 : (row > H_IMG - 1 ? H_IMG - 1 : row);
            unsigned long long vlo, vhi;
            if (inb) {
                ulonglong2 v = __ldg((const ulonglong2*)inc
                                     + (size_t)row * (W_IMG / 4) + gfc);
                vlo = v.x; vhi = v.y;
            } else {
                float s = __ldg(inc + (size_t)row * W_IMG + cadj);
                vlo = pack2(s, s); vhi = vlo;
            }
#pragma unroll
            for (int i = 0; i < 4; ++i) {
                int d = r - RADIUS - i;      // compile-time per (r,i)
                if (d >= -RADIUS && d <= RADIUS) {
                    unsigned long long w = w2[d < 0 ? -d : d];
                    fma2(aLo[i], vlo, w);
                    fma2(aHi[i], vhi, w);
                }
            }
        }

        // Transpose-store y-pairs, swizzled 16B slots. Slot u (2 x-positions)
        // of plane p holds (even[x], odd[x], even[x+1], odd[x+1]).
#pragma unroll
        for (int j = 0; j < 2; ++j) {        // row-pair within ygroup
            float a0x, a0y, a0z, a0w, a1x, a1y, a1z, a1w;
            unpack2(aLo[2 * j],     a0x, a0y); unpack2(aHi[2 * j],     a0z, a0w);
            unpack2(aLo[2 * j + 1], a1x, a1y); unpack2(aHi[2 * j + 1], a1z, a1w);
            int plane = 2 * yg + j;
            int u0 = 2 * c, u1 = 2 * c + 1;
            int p0 = u0 ^ ((u0 >> 3) & 7);
            int p1 = u1 ^ ((u1 >> 3) & 7);
            *(float4*)&vt[plane * 512 + p0 * 4] = make_float4(a0x, a1x, a0y, a1y);
            *(float4*)&vt[plane * 512 + p1 * 4] = make_float4(a0z, a1z, a0w, a1w);
        }
    }

    __syncthreads();

    // ------------------------ Horizontal phase -------------------------
    // 232 threads: 8 row-pairs (one warp each) x 29 x-slots of 8 px. Window
    // = 16 swizzled LDS.128; each loaded u64 is a ready y-pair operand.
    {
        int rp = t >> 5;                     // row-pair 0..7
        int s  = t & 31;                     // x-slot
        int X0 = OW * bx + 8 * s;            // global float col of px 0
        if (s < 29 && X0 < W_IMG) {
            unsigned long long acc[8];
#pragma unroll
            for (int p = 0; p < 8; ++p) acc[p] = 0ull;

            const float* pl = &vt[rp * 512];
#pragma unroll
            for (int m = 0; m < 16; ++m) {
                int u  = 4 * s + m;
                int ph = u ^ ((u >> 3) & 7);
                ulonglong2 q = *(const ulonglong2*)&pl[ph * 4];
#pragma unroll
                for (int k = 0; k < 2; ++k) {
                    unsigned long long f = k ? q.y : q.x;
                    int xo = 2 * m + k;      // window offset 0..31
#pragma unroll
                    for (int p = 0; p < 8; ++p) {
                        int d = xo - RADIUS - p;   // compile-time
                        if (d >= -RADIUS && d <= RADIUS)
                            fma2(acc[p], f, w2[d < 0 ? -d : d]);
                    }
                }
            }

            float lo[8], hi[8];
#pragma unroll
            for (int p = 0; p < 8; ++p) unpack2(acc[p], lo[p], hi[p]);
            size_t ob = (size_t)cch * ((size_t)H_IMG * W_IMG)
                      + (size_t)(y0 + 2 * rp) * W_IMG + X0;
            *(float4*)&out[ob]             = make_float4(lo[0], lo[1], lo[2], lo[3]);
            *(float4*)&out[ob + 4]         = make_float4(lo[4], lo[5], lo[6], lo[7]);
            *(float4*)&out[ob + W_IMG]     = make_float4(hi[0], hi[1], hi[2], hi[3]);
            *(float4*)&out[ob + W_IMG + 4] = make_float4(hi[4], hi[5], hi[6], hi[7]);
        }
    }
}

// ------------------------------ entry point --------------------------------
extern "C" void kernel_launch(void* const* d_in, const int* in_sizes, int n_in,
                              void* d_out, int out_size) {
    const float* img = (const float*)d_in[0];    // [1,3,4096,4096] fp32
    float* out = (float*)d_out;                  // [3,4096,4096] fp32

    dim3 grid(TILES_X, H_IMG / OH, C_IMG);       // (18, 256, 3)
    fused_blur_kernel<<<grid, 256>>>(img, out);
}

// round 8
// speedup vs baseline: 1.9149x; 1.5664x over previous
#include <cuda_runtime.h>
#include <cuda_fp16.h>

// ---------------------------------------------------------------------------
// KNNGaussianBlur: out = GaussianBlur_sigma4_radius12(img[0]) with replicate
// padding. (/max ... *max cancels -> no reduction.)
//
// R8: two-pass (R4 skeleton -- fusion proven L1-wavefront-negative in R5-R7)
// with FP16 SCRATCH:
//  * DRAM crossing traffic 804 -> 603 MB
//  * hblur loads halve in bytes: window for 8 outputs = 32 halves = 5
//    coalesced 16B loads (vs 7 f4 per 4 outputs in R4)
//  * error bound is deterministic: scratch v in [0,1), all taps positive ->
//    rel err <= 2^-12 per output ~ 2.4e-4 << 1e-3 threshold.
// V accumulates fp32; H converts half->float and accumulates fp32.
// ---------------------------------------------------------------------------

#define H_IMG 4096
#define W_IMG 4096
#define C_IMG 3
#define RADIUS 12

// 100.7 MB fp16 scratch (device global: allocation in kernel_launch is banned).
__device__ __half g_scratch[(size_t)C_IMG * H_IMG * W_IMG];

// 13 unique weights, compile-time constants -> FFMA-imm (rt_SMSP=1).
__device__ constexpr float KW[13] = {
    0.09990835f, 0.09683452f, 0.08816879f, 0.07541476f, 0.06059747f,
    0.04574137f, 0.03243549f, 0.02160670f, 0.01352113f, 0.00794866f,
    0.00438966f, 0.00227733f, 0.00110988f
};

// ------------------------------ Vertical pass ------------------------------
// R4's proven shape: thread = one f4 column x 16 output rows, 40-row stream,
// row clamp = replicate pad. Store converts to half4 (8B, coalesced 2 wf).
constexpr int VROWS = 16;

__global__ __launch_bounds__(128)
void vblur_kernel(const float4* __restrict__ in) {
    const int W4 = W_IMG / 4;                      // 1024
    int col4 = blockIdx.x * 128 + threadIdx.x;     // 0..1023
    int y0   = blockIdx.y * VROWS;
    int cch  = blockIdx.z;

    const float4* inc  = in + (size_t)cch * ((size_t)H_IMG * W4);
    __half*       outc = g_scratch + (size_t)cch * ((size_t)H_IMG * W_IMG);

    float4 acc[VROWS];
#pragma unroll
    for (int i = 0; i < VROWS; ++i) acc[i] = make_float4(0.f, 0.f, 0.f, 0.f);

#pragma unroll
    for (int rr = 0; rr < VROWS + 2 * RADIUS; ++rr) {
        int row = y0 - RADIUS + rr;
        row = row < 0 ? 0 : (row > H_IMG - 1 ? H_IMG - 1 : row);
        float4 v = __ldg(&inc[(size_t)row * W4 + col4]);
#pragma unroll
        for (int i = 0; i < VROWS; ++i) {
            int d = rr - RADIUS - i;               // compile-time per (rr,i)
            if (d >= -RADIUS && d <= RADIUS) {
                float w = KW[d < 0 ? -d : d];
                acc[i].x = fmaf(v.x, w, acc[i].x);
                acc[i].y = fmaf(v.y, w, acc[i].y);
                acc[i].z = fmaf(v.z, w, acc[i].z);
                acc[i].w = fmaf(v.w, w, acc[i].w);
            }
        }
    }

#pragma unroll
    for (int i = 0; i < VROWS; ++i) {
        __half2 lo = __floats2half2_rn(acc[i].x, acc[i].y);
        __half2 hi = __floats2half2_rn(acc[i].z, acc[i].w);
        uint2 pk = make_uint2(*(unsigned*)&lo, *(unsigned*)&hi);
        *(uint2*)(outc + (size_t)(y0 + i) * W_IMG + 4 * (size_t)col4) = pk;
    }
}

// ----------------------------- Horizontal pass -----------------------------
// Block = 256 thr = 8 warps = one row. Warp w owns px [512w, 512w+512) in 2
// groups; lane t of group g owns half8-slot b8 = 64w+32g+t (8 consecutive px,
// base = 8*b8). Window = halves [base-12, base+19] c slots [b8-2, b8+2]:
// 5 LDG.16B, consecutive slots across lanes -> fully coalesced (4 wf/instr).
// OOB slots are entirely outside the image -> broadcast edge pixel (exact
// replicate padding; in-range slots never need clamping since W=4096=512*8).
// Streamed convert+FMA keeps live set small (no 40-float array).
__global__ __launch_bounds__(256)
void hblur_kernel(float* __restrict__ out) {
    int row  = blockIdx.x;
    int cch  = blockIdx.y;
    int w    = threadIdx.x >> 5;
    int lane = threadIdx.x & 31;

    size_t rbase = ((size_t)cch * H_IMG + row) * W_IMG;
    const __half* inr  = g_scratch + rbase;
    const uint4*  in16 = (const uint4*)inr;        // 512 slots of 8 halves

#pragma unroll
    for (int g = 0; g < 2; ++g) {
        int b8   = 64 * w + 32 * g + lane;         // owned slot 0..511
        int base = 8 * b8;                         // first output px

        float acc[8];
#pragma unroll
        for (int p = 0; p < 8; ++p) acc[p] = 0.f;

#pragma unroll
        for (int j = 0; j < 5; ++j) {
            int s = b8 - 2 + j;
            uint4 q;
            if (s >= 0 && s < W_IMG / 8) {
                q = __ldg(&in16[s]);
            } else {
                __half e = __ldg(&inr[s < 0 ? 0 : W_IMG - 1]);
                unsigned he = (unsigned)__half_as_ushort(e);
                he |= he << 16;
                q = make_uint4(he, he, he, he);
            }
            // 8 halves of this slot: input px = 8*(b8-2+j) + e = base-16+8j+e
#pragma unroll
            for (int h2i = 0; h2i < 4; ++h2i) {
                unsigned uq = (h2i == 0) ? q.x : (h2i == 1) ? q.y
                            : (h2i == 2) ? q.z : q.w;
                float2 f2 = __half22float2(*(__half2*)&uq);
#pragma unroll
                for (int k = 0; k < 2; ++k) {
                    int m  = 8 * j + 2 * h2i + k;  // 0..39, compile-time
                    float xv = k ? f2.y : f2.x;
#pragma unroll
                    for (int p = 0; p < 8; ++p) {
                        int d = m - 16 - p;        // compile-time tap offset
                        if (d >= -RADIUS && d <= RADIUS)
                            acc[p] = fmaf(xv, KW[d < 0 ? -d : d], acc[p]);
                    }
                }
            }
        }

        float* o = out + rbase + base;
        *(float4*)o       = make_float4(acc[0], acc[1], acc[2], acc[3]);
        *(float4*)(o + 4) = make_float4(acc[4], acc[5], acc[6], acc[7]);
    }
}

// ------------------------------ entry point --------------------------------
extern "C" void kernel_launch(void* const* d_in, const int* in_sizes, int n_in,
                              void* d_out, int out_size) {
    const float* img = (const float*)d_in[0];      // [1,3,4096,4096] fp32
    float* out = (float*)d_out;                    // [3,4096,4096] fp32

    dim3 vgrid(W_IMG / 4 / 128, H_IMG / VROWS, C_IMG);   // (8, 256, 3)
    vblur_kernel<<<vgrid, 128>>>((const float4*)img);

    dim3 hgrid(H_IMG, C_IMG);                            // (4096, 3)
    hblur_kernel<<<hgrid, 256>>>(out);
}